// round 13
// baseline (speedup 1.0000x reference)
#include <cuda_runtime.h>
#include <cuda_fp16.h>
#include <mma.h>
#include <stdint.h>

using namespace nvcuda;

#define MAXN 100000
#define MAXE 1600000
#define HID  64
#define CAP  128   // max in-degree capacity (Poisson(16): P(deg>=128) ~ 0)

// ---------------- device scratch (zero-initialized at module load) ----------------
static __device__ __align__(256) int    g_cnt[MAXN];                    // 0 at entry; re-zeroed by k_agg2
static __device__ __align__(256) int    g_slot[(size_t)MAXN * CAP];     // bucketed source lists
static __device__ __align__(256) __half g_hs[(size_t)MAXN * HID];       // dinv-scaled GEMM output (fp16)
static __device__ __align__(256) __half g_a[(size_t)MAXN * HID];        // layer-1 activations (fp16)

// ---------------- bucket fill: one pass, count + insert, 8 edges per thread ----------------
__global__ void k_fill(const int* __restrict__ src, const int* __restrict__ dst, int e) {
    int base = (blockIdx.x * blockDim.x + threadIdx.x) << 3;
    if (base >= e) return;
    if (base + 8 <= e) {
        int4 da = *(const int4*)(dst + base);
        int4 db = *(const int4*)(dst + base + 4);
        int4 sa = *(const int4*)(src + base);
        int4 sb = *(const int4*)(src + base + 4);
        int p0 = atomicAdd(&g_cnt[da.x], 1);
        int p1 = atomicAdd(&g_cnt[da.y], 1);
        int p2 = atomicAdd(&g_cnt[da.z], 1);
        int p3 = atomicAdd(&g_cnt[da.w], 1);
        int p4 = atomicAdd(&g_cnt[db.x], 1);
        int p5 = atomicAdd(&g_cnt[db.y], 1);
        int p6 = atomicAdd(&g_cnt[db.z], 1);
        int p7 = atomicAdd(&g_cnt[db.w], 1);
        if (p0 < CAP) g_slot[(size_t)da.x * CAP + p0] = sa.x;
        if (p1 < CAP) g_slot[(size_t)da.y * CAP + p1] = sa.y;
        if (p2 < CAP) g_slot[(size_t)da.z * CAP + p2] = sa.z;
        if (p3 < CAP) g_slot[(size_t)da.w * CAP + p3] = sa.w;
        if (p4 < CAP) g_slot[(size_t)db.x * CAP + p4] = sb.x;
        if (p5 < CAP) g_slot[(size_t)db.y * CAP + p5] = sb.y;
        if (p6 < CAP) g_slot[(size_t)db.z * CAP + p6] = sb.z;
        if (p7 < CAP) g_slot[(size_t)db.w * CAP + p7] = sb.w;
    } else {
        for (int i = base; i < e; ++i) {
            int d = dst[i];
            int p = atomicAdd(&g_cnt[d], 1);
            if (p < CAP) g_slot[(size_t)d * CAP + p] = src[i];
        }
    }
}

// ---------------- templated wmma GEMM: hs = half( rsqrt(cnt+1)[row] * (X[n,K] @ W[K,64]) ) ----------------
// MB = min blocks/SM (occupancy floor; caps registers). gemm1: MB=4 (64-reg budget).
// gemm2: MB=6 (42-reg budget, smem 34.8KB allows 6 blocks -> 56% occ).
template<int K, typename AT, int MB>
__global__ void __launch_bounds__(256, MB)
k_gemm(const AT* __restrict__ X, const float* __restrict__ W,
       __half* __restrict__ Y, int n) {
    constexpr int LDA = K + 8;
    constexpr int ASZ = 128 * LDA * 2;          // bytes
    extern __shared__ __align__(16) unsigned char smbuf[];
    __half (*sA)[LDA]  = (__half(*)[LDA])smbuf;
    __half (*sB)[72]   = (__half(*)[72])(smbuf + ASZ);
    float  (*sOut)[68] = (float(*)[68])smbuf;   // epilogue aliases staging (needs 34816 B)

    const int tid = threadIdx.x;
    const int wid = tid >> 5;
    const int wr = wid >> 1;
    const int wc = wid & 1;
    const int rowBase = blockIdx.x * 128;

    // stage A
    if constexpr (sizeof(AT) == 4) {            // fp32 -> fp16 convert
        constexpr int kq = K >> 2;
        for (int i = tid; i < (128 * K) >> 2; i += 256) {
            int r = i / kq, q = i % kq;
            int row = rowBase + r;
            float4 v = make_float4(0.f, 0.f, 0.f, 0.f);
            if (row < n)
                v = *(const float4*)((const float*)X + (size_t)row * K + (q << 2));
            *(__half2*)&sA[r][(q << 2)]     = __floats2half2_rn(v.x, v.y);
            *(__half2*)&sA[r][(q << 2) + 2] = __floats2half2_rn(v.z, v.w);
        }
    } else {                                    // fp16 direct copy (8 halves per uint4)
        constexpr int kq8 = K >> 3;
        for (int i = tid; i < (128 * K) >> 3; i += 256) {
            int r = i / kq8, q = i % kq8;
            int row = rowBase + r;
            uint4 v = make_uint4(0u, 0u, 0u, 0u);
            if (row < n)
                v = *(const uint4*)((const __half*)X + (size_t)row * K + (q << 3));
            *(uint4*)&sA[r][q << 3] = v;
        }
    }
    // stage B (fp32 -> fp16)
    for (int i = tid; i < K * 16; i += 256) {
        int r = i >> 4, q = i & 15;
        float4 v = *(const float4*)(W + (size_t)r * 64 + (q << 2));
        *(__half2*)&sB[r][(q << 2)]     = __floats2half2_rn(v.x, v.y);
        *(__half2*)&sB[r][(q << 2) + 2] = __floats2half2_rn(v.z, v.w);
    }
    __syncthreads();

    wmma::fragment<wmma::accumulator, 16, 16, 16, float> acc[2][2];
#pragma unroll
    for (int i = 0; i < 2; ++i)
#pragma unroll
        for (int j = 0; j < 2; ++j) wmma::fill_fragment(acc[i][j], 0.0f);

#pragma unroll
    for (int kk = 0; kk < K; kk += 16) {
        wmma::fragment<wmma::matrix_a, 16, 16, 16, __half, wmma::row_major> a0, a1;
        wmma::fragment<wmma::matrix_b, 16, 16, 16, __half, wmma::row_major> b0, b1;
        wmma::load_matrix_sync(a0, &sA[wr * 32][kk], LDA);
        wmma::load_matrix_sync(a1, &sA[wr * 32 + 16][kk], LDA);
        wmma::load_matrix_sync(b0, &sB[kk][wc * 32], 72);
        wmma::load_matrix_sync(b1, &sB[kk][wc * 32 + 16], 72);
        wmma::mma_sync(acc[0][0], a0, b0, acc[0][0]);
        wmma::mma_sync(acc[0][1], a0, b1, acc[0][1]);
        wmma::mma_sync(acc[1][0], a1, b0, acc[1][0]);
        wmma::mma_sync(acc[1][1], a1, b1, acc[1][1]);
    }
    __syncthreads();

#pragma unroll
    for (int i = 0; i < 2; ++i)
#pragma unroll
        for (int j = 0; j < 2; ++j)
            wmma::store_matrix_sync(&sOut[wr * 32 + i * 16][wc * 32 + j * 16],
                                    acc[i][j], 68, wmma::mem_row_major);
    __syncthreads();

    // epilogue: scale by rsqrt(cnt[row]+1), fp32 -> fp16 store; 2 threads per row
    {
        int r = tid >> 1;
        int cb = (tid & 1) << 5;
        int row = rowBase + r;
        if (row < n) {
            float s = rsqrtf((float)g_cnt[row] + 1.0f);
#pragma unroll
            for (int jj = 0; jj < 4; ++jj) {
                float4 v0 = *(float4*)&sOut[r][cb + (jj << 3)];
                float4 v1 = *(float4*)&sOut[r][cb + (jj << 3) + 4];
                __half2 h[4];
                h[0] = __floats2half2_rn(v0.x * s, v0.y * s);
                h[1] = __floats2half2_rn(v0.z * s, v0.w * s);
                h[2] = __floats2half2_rn(v1.x * s, v1.y * s);
                h[3] = __floats2half2_rn(v1.z * s, v1.w * s);
                *(uint4*)(Y + (size_t)row * 64 + cb + (jj << 3)) = *(uint4*)h;
            }
        }
    }
}

#define GEMM1_SMEM (128 * 136 * 2 + 128 * 72 * 2)   // 53248
#define GEMM2_SMEM 34816                             // max(stage 27648, epilogue 34816)

// ---------------- aggregation core (R7 shape + slot-index prefetch pipeline) ----------------
__device__ __forceinline__ void acc_row8(float acc[8], uint4 hv) {
    __half2* h2 = (__half2*)&hv;
#pragma unroll
    for (int k = 0; k < 4; ++k) {
        float2 f = __half22float2(h2[k]);
        acc[2 * k]     += f.x;
        acc[2 * k + 1] += f.y;
    }
}

__device__ __forceinline__ int agg_core(const __half* __restrict__ hs,
                                        int w, int q, int r,
                                        float acc[8]) {
#pragma unroll
    for (int k = 0; k < 8; ++k) acc[k] = 0.f;

    const __half* base = hs + (r << 3);
    if (q == 0)   // self term, counted once
        acc_row8(acc, *(const uint4*)(base + (size_t)w * 64));

    const int deg = g_cnt[w];
    const int* slotrow = g_slot + (size_t)w * CAP;

    // software pipeline: fetch slot index one iteration ahead so the
    // index-load latency hides under the current row gather.
    int s_cur = (q < deg) ? slotrow[q] : -1;
    for (int t = 0; t < deg; t += 4) {
        int nidx = t + 4 + q;
        int s_nxt = (nidx < deg) ? slotrow[nidx] : -1;
        if (s_cur >= 0)
            acc_row8(acc, *(const uint4*)(base + (size_t)s_cur * 64));
        s_cur = s_nxt;
    }
#pragma unroll
    for (int k = 0; k < 8; ++k) {
        acc[k] += __shfl_xor_sync(0xffffffffu, acc[k], 8);
        acc[k] += __shfl_xor_sync(0xffffffffu, acc[k], 16);
    }
    return deg;
}

// ---------------- layer 1: a[d] = half( relu(dinv[d]*(hs[d]+sum hs[s]) + b1) ) ----------------
__global__ void k_agg1(const __half* __restrict__ hs, __half* __restrict__ a,
                       const float* __restrict__ b1, int n) {
    int w = (blockIdx.x * blockDim.x + threadIdx.x) >> 5;
    if (w >= n) return;
    int lane = threadIdx.x & 31;
    int q = lane >> 3, r = lane & 7;

    float acc[8];
    int deg = agg_core(hs, w, q, r, acc);

    if (q == 0) {
        float dvw = rsqrtf((float)deg + 1.0f);
        float4 b0 = *(const float4*)(b1 + (r << 3));
        float4 b1v = *(const float4*)(b1 + (r << 3) + 4);
        __half2 h[4];
        h[0] = __floats2half2_rn(fmaxf(acc[0] * dvw + b0.x, 0.f),
                                 fmaxf(acc[1] * dvw + b0.y, 0.f));
        h[1] = __floats2half2_rn(fmaxf(acc[2] * dvw + b0.z, 0.f),
                                 fmaxf(acc[3] * dvw + b0.w, 0.f));
        h[2] = __floats2half2_rn(fmaxf(acc[4] * dvw + b1v.x, 0.f),
                                 fmaxf(acc[5] * dvw + b1v.y, 0.f));
        h[3] = __floats2half2_rn(fmaxf(acc[6] * dvw + b1v.z, 0.f),
                                 fmaxf(acc[7] * dvw + b1v.w, 0.f));
        *(uint4*)(a + (size_t)w * 64 + (r << 3)) = *(uint4*)h;
    }
}

// ---------------- layer 2 + classifier; also re-zeroes g_cnt ----------------
__global__ void k_agg2(const __half* __restrict__ hs,
                       const float* __restrict__ b2, const float* __restrict__ Wc,
                       const float* __restrict__ bc, float* __restrict__ logits, int n) {
    int w = (blockIdx.x * blockDim.x + threadIdx.x) >> 5;
    if (w >= n) return;
    int lane = threadIdx.x & 31;
    int q = lane >> 3, r = lane & 7;

    float acc[8];
    int deg = agg_core(hs, w, q, r, acc);

    float dvw = rsqrtf((float)deg + 1.0f);
    float4 b0 = *(const float4*)(b2 + (r << 3));
    float4 b1v = *(const float4*)(b2 + (r << 3) + 4);
    float4 wc0 = *(const float4*)(Wc + (r << 3));
    float4 wc1 = *(const float4*)(Wc + (r << 3) + 4);
    float sum =
        fmaxf(acc[0] * dvw + b0.x, 0.f) * wc0.x +
        fmaxf(acc[1] * dvw + b0.y, 0.f) * wc0.y +
        fmaxf(acc[2] * dvw + b0.z, 0.f) * wc0.z +
        fmaxf(acc[3] * dvw + b0.w, 0.f) * wc0.w +
        fmaxf(acc[4] * dvw + b1v.x, 0.f) * wc1.x +
        fmaxf(acc[5] * dvw + b1v.y, 0.f) * wc1.y +
        fmaxf(acc[6] * dvw + b1v.z, 0.f) * wc1.z +
        fmaxf(acc[7] * dvw + b1v.w, 0.f) * wc1.w;
    sum += __shfl_xor_sync(0xffffffffu, sum, 1);
    sum += __shfl_xor_sync(0xffffffffu, sum, 2);
    sum += __shfl_xor_sync(0xffffffffu, sum, 4);
    if (lane == 0) {
        logits[w] = sum + bc[0];
        g_cnt[w] = 0;          // ready for next call (replay determinism)
    }
}

// ---------------- launcher ----------------
extern "C" void kernel_launch(void* const* d_in, const int* in_sizes, int n_in,
                              void* d_out, int out_size) {
    const float* x  = (const float*)d_in[0];
    const int*   ei = (const int*)d_in[1];   // int32 (JAX x64 disabled)
    const float* W1 = (const float*)d_in[2];
    const float* b1 = (const float*)d_in[3];
    const float* W2 = (const float*)d_in[4];
    const float* b2 = (const float*)d_in[5];
    const float* Wc = (const float*)d_in[6];
    const float* bc = (const float*)d_in[7];
    float* logits = (float*)d_out;

    const int n = in_sizes[0] / 128;
    const int e = in_sizes[1] / 2;
    const int* src = ei;
    const int* dst = ei + e;

    __half *p_hs, *p_a;
    cudaGetSymbolAddress((void**)&p_hs, g_hs);
    cudaGetSymbolAddress((void**)&p_a,  g_a);

    static bool attr_done = false;
    if (!attr_done) {
        cudaFuncSetAttribute((const void*)k_gemm<128, float, 4>,
                             cudaFuncAttributeMaxDynamicSharedMemorySize, GEMM1_SMEM);
        cudaFuncSetAttribute((const void*)k_gemm<64, __half, 6>,
                             cudaFuncAttributeMaxDynamicSharedMemorySize, GEMM2_SMEM);
        attr_done = true;
    }

    const int T = 256;

    // 1: bucket fill (count + insert, MLP=8)
    k_fill<<<((e >> 3) + T - 1) / T, T>>>(src, dst, e);
    // 2: layer-1 GEMM (fp32 in, fp16 out, MB=4)
    k_gemm<128, float, 4><<<(n + 127) / 128, T, GEMM1_SMEM>>>(x, W1, p_hs, n);
    // 3: layer-1 aggregation (pipelined slot prefetch)
    k_agg1<<<(n * 32 + T - 1) / T, T>>>(p_hs, p_a, b1, n);
    // 4: layer-2 GEMM (fp16 in, MB=6 — profiled launch, A/B vs R12 17.5us)
    k_gemm<64, __half, 6><<<(n + 127) / 128, T, GEMM2_SMEM>>>(p_a, W2, p_hs, n);
    // 5: layer-2 aggregation + classifier
    k_agg2<<<(n * 32 + T - 1) / T, T>>>(p_hs, b2, Wc, bc, logits, n);
}

// round 14
// speedup vs baseline: 1.0308x; 1.0308x over previous
#include <cuda_runtime.h>
#include <cuda_fp16.h>
#include <mma.h>
#include <stdint.h>

using namespace nvcuda;

#define MAXN 100000
#define MAXE 1600000
#define HID  64
#define CAP  128   // max in-degree capacity (Poisson(16): P(deg>=128) ~ 0)

// ---------------- device scratch (zero-initialized at module load) ----------------
static __device__ __align__(256) int    g_cnt[MAXN];                    // 0 at entry; re-zeroed by k_agg2
static __device__ __align__(256) int    g_slot[(size_t)MAXN * CAP];     // bucketed source lists
static __device__ __align__(256) __half g_hs[(size_t)MAXN * HID];       // dinv-scaled GEMM output (fp16)
static __device__ __align__(256) float  g_a[(size_t)MAXN * HID];        // layer-1 activations (fp32)

// ---------------- bucket fill: one pass, count + insert, 8 edges per thread ----------------
__global__ void k_fill(const int* __restrict__ src, const int* __restrict__ dst, int e) {
    int base = (blockIdx.x * blockDim.x + threadIdx.x) << 3;
    if (base >= e) return;
    if (base + 8 <= e) {
        int4 da = *(const int4*)(dst + base);
        int4 db = *(const int4*)(dst + base + 4);
        int4 sa = *(const int4*)(src + base);
        int4 sb = *(const int4*)(src + base + 4);
        int p0 = atomicAdd(&g_cnt[da.x], 1);
        int p1 = atomicAdd(&g_cnt[da.y], 1);
        int p2 = atomicAdd(&g_cnt[da.z], 1);
        int p3 = atomicAdd(&g_cnt[da.w], 1);
        int p4 = atomicAdd(&g_cnt[db.x], 1);
        int p5 = atomicAdd(&g_cnt[db.y], 1);
        int p6 = atomicAdd(&g_cnt[db.z], 1);
        int p7 = atomicAdd(&g_cnt[db.w], 1);
        if (p0 < CAP) g_slot[(size_t)da.x * CAP + p0] = sa.x;
        if (p1 < CAP) g_slot[(size_t)da.y * CAP + p1] = sa.y;
        if (p2 < CAP) g_slot[(size_t)da.z * CAP + p2] = sa.z;
        if (p3 < CAP) g_slot[(size_t)da.w * CAP + p3] = sa.w;
        if (p4 < CAP) g_slot[(size_t)db.x * CAP + p4] = sb.x;
        if (p5 < CAP) g_slot[(size_t)db.y * CAP + p5] = sb.y;
        if (p6 < CAP) g_slot[(size_t)db.z * CAP + p6] = sb.z;
        if (p7 < CAP) g_slot[(size_t)db.w * CAP + p7] = sb.w;
    } else {
        for (int i = base; i < e; ++i) {
            int d = dst[i];
            int p = atomicAdd(&g_cnt[d], 1);
            if (p < CAP) g_slot[(size_t)d * CAP + p] = src[i];
        }
    }
}

// ---------------- wmma GEMM: hs = half( rsqrt(cnt+1)[row] * (X[n,K] @ W[K,64]) ) ----------------
// 64-row tiles, 128 threads (4 warps, 2x2 warp grid), K staged once. No reg cap (R13 lesson).
// More blocks/SM (6-9 vs 4) hides the stage->mma->epilogue latency chain.
template<int K, typename AT>
__global__ void k_gemm(const AT* __restrict__ X, const float* __restrict__ W,
                       __half* __restrict__ Y, int n) {
    constexpr int LDA = K + 8;
    constexpr int ASZ = 64 * LDA * 2;           // bytes (A staging)
    extern __shared__ __align__(16) unsigned char smbuf[];
    __half (*sA)[LDA]  = (__half(*)[LDA])smbuf;
    __half (*sB)[72]   = (__half(*)[72])(smbuf + ASZ);
    float  (*sOut)[68] = (float(*)[68])smbuf;   // epilogue aliases staging (17408 B)

    const int tid = threadIdx.x;
    const int wid = tid >> 5;
    const int wr = wid >> 1;          // 0..1 : 32-row band
    const int wc = wid & 1;           // 0..1 : 32-col band
    const int rowBase = blockIdx.x * 64;

    // stage A: 64 rows x K
    if constexpr (sizeof(AT) == 4) {            // fp32 -> fp16 convert
        constexpr int kq = K >> 2;
        for (int i = tid; i < (64 * K) >> 2; i += 128) {
            int r = i / kq, q = i % kq;
            int row = rowBase + r;
            float4 v = make_float4(0.f, 0.f, 0.f, 0.f);
            if (row < n)
                v = *(const float4*)((const float*)X + (size_t)row * K + (q << 2));
            *(__half2*)&sA[r][(q << 2)]     = __floats2half2_rn(v.x, v.y);
            *(__half2*)&sA[r][(q << 2) + 2] = __floats2half2_rn(v.z, v.w);
        }
    } else {                                    // fp16 direct copy
        constexpr int kq8 = K >> 3;
        for (int i = tid; i < (64 * K) >> 3; i += 128) {
            int r = i / kq8, q = i % kq8;
            int row = rowBase + r;
            uint4 v = make_uint4(0u, 0u, 0u, 0u);
            if (row < n)
                v = *(const uint4*)((const __half*)X + (size_t)row * K + (q << 3));
            *(uint4*)&sA[r][q << 3] = v;
        }
    }
    // stage B: K rows x 64 cols (fp32 -> fp16)
    for (int i = tid; i < K * 16; i += 128) {
        int r = i >> 4, q = i & 15;
        float4 v = *(const float4*)(W + (size_t)r * 64 + (q << 2));
        *(__half2*)&sB[r][(q << 2)]     = __floats2half2_rn(v.x, v.y);
        *(__half2*)&sB[r][(q << 2) + 2] = __floats2half2_rn(v.z, v.w);
    }
    __syncthreads();

    wmma::fragment<wmma::accumulator, 16, 16, 16, float> acc[2][2];
#pragma unroll
    for (int i = 0; i < 2; ++i)
#pragma unroll
        for (int j = 0; j < 2; ++j) wmma::fill_fragment(acc[i][j], 0.0f);

#pragma unroll
    for (int kk = 0; kk < K; kk += 16) {
        wmma::fragment<wmma::matrix_a, 16, 16, 16, __half, wmma::row_major> a0, a1;
        wmma::fragment<wmma::matrix_b, 16, 16, 16, __half, wmma::row_major> b0, b1;
        wmma::load_matrix_sync(a0, &sA[wr * 32][kk], LDA);
        wmma::load_matrix_sync(a1, &sA[wr * 32 + 16][kk], LDA);
        wmma::load_matrix_sync(b0, &sB[kk][wc * 32], 72);
        wmma::load_matrix_sync(b1, &sB[kk][wc * 32 + 16], 72);
        wmma::mma_sync(acc[0][0], a0, b0, acc[0][0]);
        wmma::mma_sync(acc[0][1], a0, b1, acc[0][1]);
        wmma::mma_sync(acc[1][0], a1, b0, acc[1][0]);
        wmma::mma_sync(acc[1][1], a1, b1, acc[1][1]);
    }
    __syncthreads();

#pragma unroll
    for (int i = 0; i < 2; ++i)
#pragma unroll
        for (int j = 0; j < 2; ++j)
            wmma::store_matrix_sync(&sOut[wr * 32 + i * 16][wc * 32 + j * 16],
                                    acc[i][j], 68, wmma::mem_row_major);
    __syncthreads();

    // epilogue: scale by rsqrt(cnt[row]+1), fp32 -> fp16 store; 2 threads per row
    {
        int r = tid >> 1;
        int cb = (tid & 1) << 5;
        int row = rowBase + r;
        if (row < n) {
            float s = rsqrtf((float)g_cnt[row] + 1.0f);
#pragma unroll
            for (int jj = 0; jj < 4; ++jj) {
                float4 v0 = *(float4*)&sOut[r][cb + (jj << 3)];
                float4 v1 = *(float4*)&sOut[r][cb + (jj << 3) + 4];
                __half2 h[4];
                h[0] = __floats2half2_rn(v0.x * s, v0.y * s);
                h[1] = __floats2half2_rn(v0.z * s, v0.w * s);
                h[2] = __floats2half2_rn(v1.x * s, v1.y * s);
                h[3] = __floats2half2_rn(v1.z * s, v1.w * s);
                *(uint4*)(Y + (size_t)row * 64 + cb + (jj << 3)) = *(uint4*)h;
            }
        }
    }
}

#define GEMM1_SMEM (64 * 136 * 2 + 128 * 72 * 2)   // 17408 + 18432 = 35840
#define GEMM2_SMEM (64 * 72 * 2 + 64 * 72 * 2)     // 18432 (>= epilogue 17408)

// ---------------- aggregation core (exact R7/R11 shape, fp16 messages) ----------------
__device__ __forceinline__ void acc_row8(float acc[8], uint4 hv) {
    __half2* h2 = (__half2*)&hv;
#pragma unroll
    for (int k = 0; k < 4; ++k) {
        float2 f = __half22float2(h2[k]);
        acc[2 * k]     += f.x;
        acc[2 * k + 1] += f.y;
    }
}

__device__ __forceinline__ int agg_core(const __half* __restrict__ hs,
                                        int w, int q, int r,
                                        float acc[8]) {
#pragma unroll
    for (int k = 0; k < 8; ++k) acc[k] = 0.f;

    const __half* base = hs + (r << 3);
    if (q == 0)   // self term, counted once
        acc_row8(acc, *(const uint4*)(base + (size_t)w * 64));

    const int deg = g_cnt[w];
    const int* slotrow = g_slot + (size_t)w * CAP;
    for (int t = 0; t < deg; t += 4) {
        int idx = t + q;
        if (idx < deg) {
            int s = slotrow[idx];
            acc_row8(acc, *(const uint4*)(base + (size_t)s * 64));
        }
    }
#pragma unroll
    for (int k = 0; k < 8; ++k) {
        acc[k] += __shfl_xor_sync(0xffffffffu, acc[k], 8);
        acc[k] += __shfl_xor_sync(0xffffffffu, acc[k], 16);
    }
    return deg;
}

// ---------------- layer 1: a[d] = relu(dinv[d]*(hs[d]+sum hs[s]) + b1) ----------------
__global__ void k_agg1(const __half* __restrict__ hs, float* __restrict__ a,
                       const float* __restrict__ b1, int n) {
    int w = (blockIdx.x * blockDim.x + threadIdx.x) >> 5;
    if (w >= n) return;
    int lane = threadIdx.x & 31;
    int q = lane >> 3, r = lane & 7;

    float acc[8];
    int deg = agg_core(hs, w, q, r, acc);

    if (q == 0) {
        float dvw = rsqrtf((float)deg + 1.0f);
        float4 b0 = *(const float4*)(b1 + (r << 3));
        float4 b1v = *(const float4*)(b1 + (r << 3) + 4);
        float4 o0, o1;
        o0.x = fmaxf(acc[0] * dvw + b0.x, 0.f);
        o0.y = fmaxf(acc[1] * dvw + b0.y, 0.f);
        o0.z = fmaxf(acc[2] * dvw + b0.z, 0.f);
        o0.w = fmaxf(acc[3] * dvw + b0.w, 0.f);
        o1.x = fmaxf(acc[4] * dvw + b1v.x, 0.f);
        o1.y = fmaxf(acc[5] * dvw + b1v.y, 0.f);
        o1.z = fmaxf(acc[6] * dvw + b1v.z, 0.f);
        o1.w = fmaxf(acc[7] * dvw + b1v.w, 0.f);
        *(float4*)(a + (size_t)w * 64 + (r << 3))     = o0;
        *(float4*)(a + (size_t)w * 64 + (r << 3) + 4) = o1;
    }
}

// ---------------- layer 2 + classifier; also re-zeroes g_cnt ----------------
__global__ void k_agg2(const __half* __restrict__ hs,
                       const float* __restrict__ b2, const float* __restrict__ Wc,
                       const float* __restrict__ bc, float* __restrict__ logits, int n) {
    int w = (blockIdx.x * blockDim.x + threadIdx.x) >> 5;
    if (w >= n) return;
    int lane = threadIdx.x & 31;
    int q = lane >> 3, r = lane & 7;

    float acc[8];
    int deg = agg_core(hs, w, q, r, acc);

    float dvw = rsqrtf((float)deg + 1.0f);
    float4 b0 = *(const float4*)(b2 + (r << 3));
    float4 b1v = *(const float4*)(b2 + (r << 3) + 4);
    float4 wc0 = *(const float4*)(Wc + (r << 3));
    float4 wc1 = *(const float4*)(Wc + (r << 3) + 4);
    float sum =
        fmaxf(acc[0] * dvw + b0.x, 0.f) * wc0.x +
        fmaxf(acc[1] * dvw + b0.y, 0.f) * wc0.y +
        fmaxf(acc[2] * dvw + b0.z, 0.f) * wc0.z +
        fmaxf(acc[3] * dvw + b0.w, 0.f) * wc0.w +
        fmaxf(acc[4] * dvw + b1v.x, 0.f) * wc1.x +
        fmaxf(acc[5] * dvw + b1v.y, 0.f) * wc1.y +
        fmaxf(acc[6] * dvw + b1v.z, 0.f) * wc1.z +
        fmaxf(acc[7] * dvw + b1v.w, 0.f) * wc1.w;
    sum += __shfl_xor_sync(0xffffffffu, sum, 1);
    sum += __shfl_xor_sync(0xffffffffu, sum, 2);
    sum += __shfl_xor_sync(0xffffffffu, sum, 4);
    if (lane == 0) {
        logits[w] = sum + bc[0];
        g_cnt[w] = 0;          // ready for next call (replay determinism)
    }
}

// ---------------- launcher ----------------
extern "C" void kernel_launch(void* const* d_in, const int* in_sizes, int n_in,
                              void* d_out, int out_size) {
    const float* x  = (const float*)d_in[0];
    const int*   ei = (const int*)d_in[1];   // int32 (JAX x64 disabled)
    const float* W1 = (const float*)d_in[2];
    const float* b1 = (const float*)d_in[3];
    const float* W2 = (const float*)d_in[4];
    const float* b2 = (const float*)d_in[5];
    const float* Wc = (const float*)d_in[6];
    const float* bc = (const float*)d_in[7];
    float* logits = (float*)d_out;

    const int n = in_sizes[0] / 128;
    const int e = in_sizes[1] / 2;
    const int* src = ei;
    const int* dst = ei + e;

    __half* p_hs;
    float*  p_a;
    cudaGetSymbolAddress((void**)&p_hs, g_hs);
    cudaGetSymbolAddress((void**)&p_a,  g_a);

    static bool attr_done = false;
    if (!attr_done) {
        cudaFuncSetAttribute((const void*)k_gemm<128, float>,
                             cudaFuncAttributeMaxDynamicSharedMemorySize, GEMM1_SMEM);
        cudaFuncSetAttribute((const void*)k_gemm<64, float>,
                             cudaFuncAttributeMaxDynamicSharedMemorySize, GEMM2_SMEM);
        attr_done = true;
    }

    const int T = 256;

    // 1: bucket fill (count + insert, MLP=8)
    k_fill<<<((e >> 3) + T - 1) / T, T>>>(src, dst, e);
    // 2: layer-1 GEMM (64-row tiles, 128 threads)
    k_gemm<128, float><<<(n + 63) / 64, 128, GEMM1_SMEM>>>(x, W1, p_hs, n);
    // 3: layer-1 aggregation (exact R11)
    k_agg1<<<(n * 32 + T - 1) / T, T>>>(p_hs, p_a, b1, n);
    // 4: layer-2 GEMM (profiled launch — A/B: R11 17.9 / R13 23.7 / R14)
    k_gemm<64, float><<<(n + 63) / 64, 128, GEMM2_SMEM>>>(p_a, W2, p_hs, n);
    // 5: layer-2 aggregation + classifier
    k_agg2<<<(n * 32 + T - 1) / T, T>>>(p_hs, b2, Wc, bc, logits, n);
}

// round 15
// speedup vs baseline: 1.1407x; 1.1066x over previous
#include <cuda_runtime.h>
#include <cuda_fp16.h>
#include <mma.h>
#include <stdint.h>

using namespace nvcuda;

#define MAXN 100000
#define MAXE 1600000
#define HID  64
#define CAP  128   // max in-degree capacity (Poisson(16): P(deg>=128) ~ 0)

// ---------------- device scratch (zero-initialized at module load) ----------------
static __device__ __align__(256) int    g_cnt[MAXN];                    // 0 at entry; re-zeroed by k_agg2
static __device__ __align__(256) int    g_slot[(size_t)MAXN * CAP];     // bucketed source lists
static __device__ __align__(256) __half g_hs[(size_t)MAXN * HID];       // dinv-scaled GEMM output (fp16)
static __device__ __align__(256) float  g_a[(size_t)MAXN * HID];        // layer-1 activations (fp32)

// ---------------- bucket fill: one pass, count + insert, 16 edges per thread (MLP=16) ----------------
__global__ void k_fill(const int* __restrict__ src, const int* __restrict__ dst, int e) {
    int base = (blockIdx.x * blockDim.x + threadIdx.x) << 4;
    if (base >= e) return;
    if (base + 16 <= e) {
        int4 d0 = *(const int4*)(dst + base);
        int4 d1 = *(const int4*)(dst + base + 4);
        int4 d2 = *(const int4*)(dst + base + 8);
        int4 d3 = *(const int4*)(dst + base + 12);
        int4 s0 = *(const int4*)(src + base);
        int4 s1 = *(const int4*)(src + base + 4);
        int4 s2 = *(const int4*)(src + base + 8);
        int4 s3 = *(const int4*)(src + base + 12);
        int p0  = atomicAdd(&g_cnt[d0.x], 1);
        int p1  = atomicAdd(&g_cnt[d0.y], 1);
        int p2  = atomicAdd(&g_cnt[d0.z], 1);
        int p3  = atomicAdd(&g_cnt[d0.w], 1);
        int p4  = atomicAdd(&g_cnt[d1.x], 1);
        int p5  = atomicAdd(&g_cnt[d1.y], 1);
        int p6  = atomicAdd(&g_cnt[d1.z], 1);
        int p7  = atomicAdd(&g_cnt[d1.w], 1);
        int p8  = atomicAdd(&g_cnt[d2.x], 1);
        int p9  = atomicAdd(&g_cnt[d2.y], 1);
        int p10 = atomicAdd(&g_cnt[d2.z], 1);
        int p11 = atomicAdd(&g_cnt[d2.w], 1);
        int p12 = atomicAdd(&g_cnt[d3.x], 1);
        int p13 = atomicAdd(&g_cnt[d3.y], 1);
        int p14 = atomicAdd(&g_cnt[d3.z], 1);
        int p15 = atomicAdd(&g_cnt[d3.w], 1);
        if (p0  < CAP) g_slot[(size_t)d0.x * CAP + p0]  = s0.x;
        if (p1  < CAP) g_slot[(size_t)d0.y * CAP + p1]  = s0.y;
        if (p2  < CAP) g_slot[(size_t)d0.z * CAP + p2]  = s0.z;
        if (p3  < CAP) g_slot[(size_t)d0.w * CAP + p3]  = s0.w;
        if (p4  < CAP) g_slot[(size_t)d1.x * CAP + p4]  = s1.x;
        if (p5  < CAP) g_slot[(size_t)d1.y * CAP + p5]  = s1.y;
        if (p6  < CAP) g_slot[(size_t)d1.z * CAP + p6]  = s1.z;
        if (p7  < CAP) g_slot[(size_t)d1.w * CAP + p7]  = s1.w;
        if (p8  < CAP) g_slot[(size_t)d2.x * CAP + p8]  = s2.x;
        if (p9  < CAP) g_slot[(size_t)d2.y * CAP + p9]  = s2.y;
        if (p10 < CAP) g_slot[(size_t)d2.z * CAP + p10] = s2.z;
        if (p11 < CAP) g_slot[(size_t)d2.w * CAP + p11] = s2.w;
        if (p12 < CAP) g_slot[(size_t)d3.x * CAP + p12] = s3.x;
        if (p13 < CAP) g_slot[(size_t)d3.y * CAP + p13] = s3.y;
        if (p14 < CAP) g_slot[(size_t)d3.z * CAP + p14] = s3.z;
        if (p15 < CAP) g_slot[(size_t)d3.w * CAP + p15] = s3.w;
    } else {
        for (int i = base; i < e; ++i) {
            int d = dst[i];
            int p = atomicAdd(&g_cnt[d], 1);
            if (p < CAP) g_slot[(size_t)d * CAP + p] = src[i];
        }
    }
}

// ---------------- wmma GEMM: hs = half( rsqrt(cnt+1)[row] * (X[n,K] @ W[K,64]) ) ----------------
// Exact R11: 256 threads (8 warps), tile 128x64, K staged once, no reg cap.
#define GEMM_SMEM 53248
__global__ void k_gemm_f16(const float* __restrict__ X, const float* __restrict__ W,
                           __half* __restrict__ Y, int n, int K) {
    extern __shared__ __align__(16) unsigned char smbuf[];
    __half (*sA)[136]  = (__half(*)[136])smbuf;                 // 34816 B
    __half (*sB)[72]   = (__half(*)[72])(smbuf + 34816);        // 18432 B
    float  (*sOut)[68] = (float(*)[68])smbuf;                   // aliases sA after compute

    const int tid = threadIdx.x;
    const int wid = tid >> 5;
    const int wr = wid >> 1;
    const int wc = wid & 1;
    const int rowBase = blockIdx.x * 128;
    const int kq = K >> 2;

    for (int i = tid; i < (128 * K) >> 2; i += 256) {
        int r = i / kq, q = i % kq;
        int row = rowBase + r;
        float4 v = make_float4(0.f, 0.f, 0.f, 0.f);
        if (row < n)
            v = *(const float4*)(X + (size_t)row * K + (q << 2));
        *(__half2*)&sA[r][(q << 2)]     = __floats2half2_rn(v.x, v.y);
        *(__half2*)&sA[r][(q << 2) + 2] = __floats2half2_rn(v.z, v.w);
    }
    for (int i = tid; i < K * 16; i += 256) {
        int r = i >> 4, q = i & 15;
        float4 v = *(const float4*)(W + (size_t)r * 64 + (q << 2));
        *(__half2*)&sB[r][(q << 2)]     = __floats2half2_rn(v.x, v.y);
        *(__half2*)&sB[r][(q << 2) + 2] = __floats2half2_rn(v.z, v.w);
    }
    __syncthreads();

    wmma::fragment<wmma::accumulator, 16, 16, 16, float> acc[2][2];
#pragma unroll
    for (int i = 0; i < 2; ++i)
#pragma unroll
        for (int j = 0; j < 2; ++j) wmma::fill_fragment(acc[i][j], 0.0f);

#pragma unroll
    for (int kk = 0; kk < 128; kk += 16) {
        if (kk >= K) break;
        wmma::fragment<wmma::matrix_a, 16, 16, 16, __half, wmma::row_major> a0, a1;
        wmma::fragment<wmma::matrix_b, 16, 16, 16, __half, wmma::row_major> b0, b1;
        wmma::load_matrix_sync(a0, &sA[wr * 32][kk], 136);
        wmma::load_matrix_sync(a1, &sA[wr * 32 + 16][kk], 136);
        wmma::load_matrix_sync(b0, &sB[kk][wc * 32], 72);
        wmma::load_matrix_sync(b1, &sB[kk][wc * 32 + 16], 72);
        wmma::mma_sync(acc[0][0], a0, b0, acc[0][0]);
        wmma::mma_sync(acc[0][1], a0, b1, acc[0][1]);
        wmma::mma_sync(acc[1][0], a1, b0, acc[1][0]);
        wmma::mma_sync(acc[1][1], a1, b1, acc[1][1]);
    }
    __syncthreads();

#pragma unroll
    for (int i = 0; i < 2; ++i)
#pragma unroll
        for (int j = 0; j < 2; ++j)
            wmma::store_matrix_sync(&sOut[wr * 32 + i * 16][wc * 32 + j * 16],
                                    acc[i][j], 68, wmma::mem_row_major);
    __syncthreads();

    {
        int r = tid >> 1;
        int cb = (tid & 1) << 5;
        int row = rowBase + r;
        if (row < n) {
            float s = rsqrtf((float)g_cnt[row] + 1.0f);
#pragma unroll
            for (int jj = 0; jj < 4; ++jj) {
                float4 v0 = *(float4*)&sOut[r][cb + (jj << 3)];
                float4 v1 = *(float4*)&sOut[r][cb + (jj << 3) + 4];
                __half2 h[4];
                h[0] = __floats2half2_rn(v0.x * s, v0.y * s);
                h[1] = __floats2half2_rn(v0.z * s, v0.w * s);
                h[2] = __floats2half2_rn(v1.x * s, v1.y * s);
                h[3] = __floats2half2_rn(v1.z * s, v1.w * s);
                *(uint4*)(Y + (size_t)row * 64 + cb + (jj << 3)) = *(uint4*)h;
            }
        }
    }
}

// ---------------- aggregation core (exact R7/R11 shape, fp16 messages) ----------------
__device__ __forceinline__ void acc_row8(float acc[8], uint4 hv) {
    __half2* h2 = (__half2*)&hv;
#pragma unroll
    for (int k = 0; k < 4; ++k) {
        float2 f = __half22float2(h2[k]);
        acc[2 * k]     += f.x;
        acc[2 * k + 1] += f.y;
    }
}

__device__ __forceinline__ int agg_core(const __half* __restrict__ hs,
                                        int w, int q, int r,
                                        float acc[8]) {
#pragma unroll
    for (int k = 0; k < 8; ++k) acc[k] = 0.f;

    const __half* base = hs + (r << 3);
    if (q == 0)   // self term, counted once
        acc_row8(acc, *(const uint4*)(base + (size_t)w * 64));

    const int deg = g_cnt[w];
    const int* slotrow = g_slot + (size_t)w * CAP;
    for (int t = 0; t < deg; t += 4) {
        int idx = t + q;
        if (idx < deg) {
            int s = slotrow[idx];
            acc_row8(acc, *(const uint4*)(base + (size_t)s * 64));
        }
    }
#pragma unroll
    for (int k = 0; k < 8; ++k) {
        acc[k] += __shfl_xor_sync(0xffffffffu, acc[k], 8);
        acc[k] += __shfl_xor_sync(0xffffffffu, acc[k], 16);
    }
    return deg;
}

// ---------------- layer 1: a[d] = relu(dinv[d]*(hs[d]+sum hs[s]) + b1) ----------------
__global__ void k_agg1(const __half* __restrict__ hs, float* __restrict__ a,
                       const float* __restrict__ b1, int n) {
    int w = (blockIdx.x * blockDim.x + threadIdx.x) >> 5;
    if (w >= n) return;
    int lane = threadIdx.x & 31;
    int q = lane >> 3, r = lane & 7;

    float acc[8];
    int deg = agg_core(hs, w, q, r, acc);

    if (q == 0) {
        float dvw = rsqrtf((float)deg + 1.0f);
        float4 b0 = *(const float4*)(b1 + (r << 3));
        float4 b1v = *(const float4*)(b1 + (r << 3) + 4);
        float4 o0, o1;
        o0.x = fmaxf(acc[0] * dvw + b0.x, 0.f);
        o0.y = fmaxf(acc[1] * dvw + b0.y, 0.f);
        o0.z = fmaxf(acc[2] * dvw + b0.z, 0.f);
        o0.w = fmaxf(acc[3] * dvw + b0.w, 0.f);
        o1.x = fmaxf(acc[4] * dvw + b1v.x, 0.f);
        o1.y = fmaxf(acc[5] * dvw + b1v.y, 0.f);
        o1.z = fmaxf(acc[6] * dvw + b1v.z, 0.f);
        o1.w = fmaxf(acc[7] * dvw + b1v.w, 0.f);
        *(float4*)(a + (size_t)w * 64 + (r << 3))     = o0;
        *(float4*)(a + (size_t)w * 64 + (r << 3) + 4) = o1;
    }
}

// ---------------- layer 2 + classifier; also re-zeroes g_cnt ----------------
__global__ void k_agg2(const __half* __restrict__ hs,
                       const float* __restrict__ b2, const float* __restrict__ Wc,
                       const float* __restrict__ bc, float* __restrict__ logits, int n) {
    int w = (blockIdx.x * blockDim.x + threadIdx.x) >> 5;
    if (w >= n) return;
    int lane = threadIdx.x & 31;
    int q = lane >> 3, r = lane & 7;

    float acc[8];
    int deg = agg_core(hs, w, q, r, acc);

    float dvw = rsqrtf((float)deg + 1.0f);
    float4 b0 = *(const float4*)(b2 + (r << 3));
    float4 b1v = *(const float4*)(b2 + (r << 3) + 4);
    float4 wc0 = *(const float4*)(Wc + (r << 3));
    float4 wc1 = *(const float4*)(Wc + (r << 3) + 4);
    float sum =
        fmaxf(acc[0] * dvw + b0.x, 0.f) * wc0.x +
        fmaxf(acc[1] * dvw + b0.y, 0.f) * wc0.y +
        fmaxf(acc[2] * dvw + b0.z, 0.f) * wc0.z +
        fmaxf(acc[3] * dvw + b0.w, 0.f) * wc0.w +
        fmaxf(acc[4] * dvw + b1v.x, 0.f) * wc1.x +
        fmaxf(acc[5] * dvw + b1v.y, 0.f) * wc1.y +
        fmaxf(acc[6] * dvw + b1v.z, 0.f) * wc1.z +
        fmaxf(acc[7] * dvw + b1v.w, 0.f) * wc1.w;
    sum += __shfl_xor_sync(0xffffffffu, sum, 1);
    sum += __shfl_xor_sync(0xffffffffu, sum, 2);
    sum += __shfl_xor_sync(0xffffffffu, sum, 4);
    if (lane == 0) {
        logits[w] = sum + bc[0];
        g_cnt[w] = 0;          // ready for next call (replay determinism)
    }
}

// ---------------- launcher ----------------
extern "C" void kernel_launch(void* const* d_in, const int* in_sizes, int n_in,
                              void* d_out, int out_size) {
    const float* x  = (const float*)d_in[0];
    const int*   ei = (const int*)d_in[1];   // int32 (JAX x64 disabled)
    const float* W1 = (const float*)d_in[2];
    const float* b1 = (const float*)d_in[3];
    const float* W2 = (const float*)d_in[4];
    const float* b2 = (const float*)d_in[5];
    const float* Wc = (const float*)d_in[6];
    const float* bc = (const float*)d_in[7];
    float* logits = (float*)d_out;

    const int n = in_sizes[0] / 128;
    const int e = in_sizes[1] / 2;
    const int* src = ei;
    const int* dst = ei + e;

    __half* p_hs;
    float*  p_a;
    cudaGetSymbolAddress((void**)&p_hs, g_hs);
    cudaGetSymbolAddress((void**)&p_a,  g_a);

    static bool attr_done = false;
    if (!attr_done) {
        cudaFuncSetAttribute(k_gemm_f16, cudaFuncAttributeMaxDynamicSharedMemorySize, GEMM_SMEM);
        attr_done = true;
    }

    const int T = 256;

    // 1: bucket fill (count + insert, MLP=16)
    k_fill<<<((e >> 4) + T - 1) / T, T>>>(src, dst, e);
    // 2: layer-1 GEMM (exact R11)
    k_gemm_f16<<<(n + 127) / 128, T, GEMM_SMEM>>>(x, W1, p_hs, n, 128);
    // 3: layer-1 aggregation (exact R11)
    k_agg1<<<(n * 32 + T - 1) / T, T>>>(p_hs, p_a, b1, n);
    // 4: layer-2 GEMM (exact R11)
    k_gemm_f16<<<(n + 127) / 128, T, GEMM_SMEM>>>(p_a, W2, p_hs, n, 64);
    // 5: layer-2 aggregation + classifier (exact R11)
    k_agg2<<<(n * 32 + T - 1) / T, T>>>(p_hs, b2, Wc, bc, logits, n);
}